// round 14
// baseline (speedup 1.0000x reference)
#include <cuda_runtime.h>
#include <math.h>

#define NN      50000
#define NE      800000
#define NHEADS  4
#define NHID    64
#define NHC     256

typedef unsigned long long ull;

// ---- packed f32x2 helpers (PTX ISA 8.6, sm_100+) ----
__device__ __forceinline__ ull pk2(float lo, float hi) {
    ull r; asm("mov.b64 %0, {%1, %2};" : "=l"(r) : "f"(lo), "f"(hi)); return r;
}
__device__ __forceinline__ void upk2(float& lo, float& hi, ull v) {
    asm("mov.b64 {%0, %1}, %2;" : "=f"(lo), "=f"(hi) : "l"(v));
}
__device__ __forceinline__ ull ffma2(ull a, ull b, ull c) {
    ull d; asm("fma.rn.f32x2 %0, %1, %2, %3;" : "=l"(d) : "l"(a), "l"(b), "l"(c)); return d;
}
__device__ __forceinline__ ull fadd2(ull a, ull b) {
    ull d; asm("add.rn.f32x2 %0, %1, %2;" : "=l"(d) : "l"(a), "l"(b)); return d;
}

// ---------------- scratch (static device globals; no allocation) ----------------
// zero-initialized at module load; k_node re-zeroes g_ACC/g_DEN each layer so
// every kernel_launch call starts from zeroed scratch (graph-replay safe).
__device__ __align__(16) float g_XL [(size_t)NN * NHC];
__device__ __align__(16) float g_XR [(size_t)NN * NHC];
__device__ __align__(16) float g_P  [(size_t)NE * NHEADS];
__device__ __align__(16) float g_DEN[(size_t)NN * NHEADS];
__device__ __align__(16) float g_ACC[(size_t)NN * NHID];
__device__ __align__(16) float g_A  [(size_t)NN * NHID];
__device__ __align__(16) int   g_SRC[NE];
__device__ __align__(16) int   g_DST[NE];

// ---------------- canonicalize edge_index (handles int32 OR int64 input) -------
__global__ void k_convert(const void* __restrict__ ei_raw) {
    __shared__ int s_is64;
    const int* ei32 = (const int*)ei_raw;
    if (threadIdx.x == 0) {
        int nz = 0;
#pragma unroll
        for (int i = 0; i < 32; i++) nz |= ei32[2 * i + 1];
        s_is64 = (nz == 0);
    }
    __syncthreads();
    int e = blockIdx.x * 256 + threadIdx.x;   // grid covers exactly NE
    if (s_is64) {
        const long long* ei64 = (const long long*)ei_raw;
        g_SRC[e] = (int)ei64[e];
        g_DST[e] = (int)ei64[NE + e];
    } else {
        g_SRC[e] = ei32[e];
        g_DST[e] = ei32[NE + e];
    }
}

// ---------------- dual GEMM: O = A[M,K] @ W[K,256] + b  (packed FFMA2) --------
template <int K>
__global__ __launch_bounds__(256) void k_gemm(
    const float* __restrict__ Aext, int useA,
    const float* __restrict__ W1, const float* __restrict__ b1,
    const float* __restrict__ W2, const float* __restrict__ b2)
{
    const float* A = useA ? g_A : Aext;
    const float* W = blockIdx.z ? W2 : W1;
    const float* b = blockIdx.z ? b2 : b1;
    float*       O = blockIdx.z ? g_XR : g_XL;

    const int m0 = blockIdx.y * 128;
    const int n0 = blockIdx.x * 128;

    __shared__ __align__(16) float sA[128][20];
    __shared__ __align__(16) float sW[16][132];

    const int tid = threadIdx.x;
    const int ty = tid >> 4, tx = tid & 15;

    ull acc2[8][4];
#pragma unroll
    for (int i = 0; i < 8; i++)
#pragma unroll
        for (int p = 0; p < 4; p++) acc2[i][p] = 0ull;

    for (int kt = 0; kt < K; kt += 16) {
#pragma unroll
        for (int u = 0; u < 2; u++) {
            int slot = tid + u * 256;
            int row = slot >> 2, ch = slot & 3;
            int gr = m0 + row;
            float4 v = make_float4(0.f, 0.f, 0.f, 0.f);
            if (gr < NN) v = *(const float4*)(A + (size_t)gr * K + kt + ch * 4);
            *(float4*)&sA[row][ch * 4] = v;
        }
#pragma unroll
        for (int u = 0; u < 2; u++) {
            int slot = tid + u * 256;
            int kk = slot >> 5, nc = (slot & 31) * 4;
            float4 v = *(const float4*)(W + (size_t)(kt + kk) * NHC + n0 + nc);
            *(float4*)&sW[kk][nc] = v;
        }
        __syncthreads();

#pragma unroll
        for (int kk = 0; kk < 16; kk++) {
            float4 w0 = *(float4*)&sW[kk][tx * 8];
            float4 w1 = *(float4*)&sW[kk][tx * 8 + 4];
            ull w2[4] = { pk2(w0.x, w0.y), pk2(w0.z, w0.w),
                          pk2(w1.x, w1.y), pk2(w1.z, w1.w) };
#pragma unroll
            for (int i = 0; i < 8; i++) {
                const float av = sA[ty * 8 + i][kk];
                const ull a2 = pk2(av, av);
#pragma unroll
                for (int p = 0; p < 4; p++)
                    acc2[i][p] = ffma2(a2, w2[p], acc2[i][p]);
            }
        }
        __syncthreads();
    }

    float4 bv0 = *(const float4*)(b + n0 + tx * 8);
    float4 bv1 = *(const float4*)(b + n0 + tx * 8 + 4);
#pragma unroll
    for (int i = 0; i < 8; i++) {
        int gr = m0 + ty * 8 + i;
        if (gr < NN) {
            float a0, a1, a2v, a3, a4, a5, a6, a7;
            upk2(a0, a1, acc2[i][0]);
            upk2(a2v, a3, acc2[i][1]);
            upk2(a4, a5, acc2[i][2]);
            upk2(a6, a7, acc2[i][3]);
            float4 o0 = make_float4(a0 + bv0.x, a1 + bv0.y, a2v + bv0.z, a3 + bv0.w);
            float4 o1 = make_float4(a4 + bv1.x, a5 + bv1.y, a6 + bv1.z, a7 + bv1.w);
            float* op = O + (size_t)gr * NHC + n0 + tx * 8;
            *(float4*)op = o0;
            *(float4*)(op + 4) = o1;
        }
    }
}

// ---------------- pass A: logits -> p = exp(logit), denominator scatter --------
// 64 threads per group, 2 edges per group per iteration (2x ILP), 3-level
// software pipeline (idx 2 ahead, rows 1 ahead) at 5 blocks/SM (20 warps).
__global__ __launch_bounds__(128, 5) void k_logits(
    const float* __restrict__ ea,
    const float* __restrict__ We, const float* __restrict__ att)
{
    const int tid   = threadIdx.x;
    const int grp   = tid >> 6;           // 0..1
    const int quad  = tid & 63;
    const int ch0   = quad * 4;
    const int head  = quad >> 4;          // 0..3

    ull wepk[9][2];
#pragma unroll
    for (int k = 0; k < 9; k++) {
        float4 w = *(const float4*)(We + k * NHC + ch0);
        wepk[k][0] = pk2(w.x, w.y);
        wepk[k][1] = pk2(w.z, w.w);
    }
    const float4 att4 = *(const float4*)(att + ch0);

    const int stride = gridDim.x * 4;     // 4 edges per block-iteration
    int e0 = blockIdx.x * 4 + grp * 2;    // even; pair (e0, e0+1)

    // ---- prologue ----
    const int sA0 = g_SRC[e0],     dA0i = g_DST[e0];
    const int sB0 = g_SRC[e0 + 1], dB0i = g_DST[e0 + 1];
    int dA0 = dA0i, dB0 = dB0i;
    int e1 = e0 + stride;
    int c1 = (e1 < NE) ? e1 : e0;
    int sA1 = g_SRC[c1],     dA1 = g_DST[c1];
    int sB1 = g_SRC[c1 + 1], dB1 = g_DST[c1 + 1];
    float4 xlA = *(const float4*)(g_XL + (size_t)sA0 * NHC + ch0);
    float4 xrA = *(const float4*)(g_XR + (size_t)dA0i * NHC + ch0);
    float4 xlB = *(const float4*)(g_XL + (size_t)sB0 * NHC + ch0);
    float4 xrB = *(const float4*)(g_XR + (size_t)dB0i * NHC + ch0);

    while (e0 < NE) {
        // ---- stage 2: prefetch indices for iter e2 ----
        const int e2 = e1 + stride;
        const int c2 = (e2 < NE) ? e2 : e0;       // clamp to a valid even edge
        const int sA2 = __ldg(&g_SRC[c2]);
        const int dA2 = __ldg(&g_DST[c2]);
        const int sB2 = __ldg(&g_SRC[c2 + 1]);
        const int dB2 = __ldg(&g_DST[c2 + 1]);

        // ---- stage 1: gather rows for iter e1 (idx already resident) ----
        const float4 xlA1 = *(const float4*)(g_XL + (size_t)sA1 * NHC + ch0);
        const float4 xrA1 = *(const float4*)(g_XR + (size_t)dA1 * NHC + ch0);
        const float4 xlB1 = *(const float4*)(g_XL + (size_t)sB1 * NHC + ch0);
        const float4 xrB1 = *(const float4*)(g_XR + (size_t)dB1 * NHC + ch0);

        // ---- stage 0: compute iter e0 ----
        ull evA01 = fadd2(pk2(xlA.x, xlA.y), pk2(xrA.x, xrA.y));
        ull evA23 = fadd2(pk2(xlA.z, xlA.w), pk2(xrA.z, xrA.w));
        ull evB01 = fadd2(pk2(xlB.x, xlB.y), pk2(xrB.x, xrB.y));
        ull evB23 = fadd2(pk2(xlB.z, xlB.w), pk2(xrB.z, xrB.w));
        const float* eapA = ea + (size_t)e0 * 9;
        const float* eapB = eapA + 9;
#pragma unroll
        for (int k = 0; k < 9; k++) {
            const float aA = __ldg(eapA + k);
            const float aB = __ldg(eapB + k);
            const ull aA2 = pk2(aA, aA);
            const ull aB2 = pk2(aB, aB);
            evA01 = ffma2(aA2, wepk[k][0], evA01);
            evA23 = ffma2(aA2, wepk[k][1], evA23);
            evB01 = ffma2(aB2, wepk[k][0], evB01);
            evB23 = ffma2(aB2, wepk[k][1], evB23);
        }
        float ax, ay, az, aw, bx, by, bz, bw;
        upk2(ax, ay, evA01); upk2(az, aw, evA23);
        upk2(bx, by, evB01); upk2(bz, bw, evB23);
        ax = (ax > 0.f) ? ax : 0.2f * ax;  ay = (ay > 0.f) ? ay : 0.2f * ay;
        az = (az > 0.f) ? az : 0.2f * az;  aw = (aw > 0.f) ? aw : 0.2f * aw;
        bx = (bx > 0.f) ? bx : 0.2f * bx;  by = (by > 0.f) ? by : 0.2f * by;
        bz = (bz > 0.f) ? bz : 0.2f * bz;  bw = (bw > 0.f) ? bw : 0.2f * bw;
        float pA = att4.x * ax;
        float pB = att4.x * bx;
        pA = fmaf(att4.y, ay, pA);  pB = fmaf(att4.y, by, pB);
        pA = fmaf(att4.z, az, pA);  pB = fmaf(att4.z, bz, pB);
        pA = fmaf(att4.w, aw, pA);  pB = fmaf(att4.w, bw, pB);

        pA += __shfl_down_sync(0xffffffffu, pA, 8, 16);
        pB += __shfl_down_sync(0xffffffffu, pB, 8, 16);
        pA += __shfl_down_sync(0xffffffffu, pA, 4, 16);
        pB += __shfl_down_sync(0xffffffffu, pB, 4, 16);
        pA += __shfl_down_sync(0xffffffffu, pA, 2, 16);
        pB += __shfl_down_sync(0xffffffffu, pB, 2, 16);
        pA += __shfl_down_sync(0xffffffffu, pA, 1, 16);
        pB += __shfl_down_sync(0xffffffffu, pB, 1, 16);

        if ((quad & 15) == 0) {
            const float expA = __expf(pA);
            const float expB = __expf(pB);
            g_P[(size_t)e0 * NHEADS + head] = expA;
            g_P[(size_t)(e0 + 1) * NHEADS + head] = expB;
            atomicAdd(&g_DEN[(size_t)dA0 * NHEADS + head], expA);
            atomicAdd(&g_DEN[(size_t)dB0 * NHEADS + head], expB);
        }

        // ---- rotate pipeline ----
        e0 = e1;  e1 = e2;
        dA0 = dA1;  dB0 = dB1;
        sA1 = sA2;  dA1 = dA2;  sB1 = sB2;  dB1 = dB2;
        xlA = xlA1; xrA = xrA1; xlB = xlB1; xrB = xrB1;
    }
}

// ---------------- invert denominators (fold 1/H head-mean in) ----------------
__global__ void k_invden() {
    int i = blockIdx.x * 256 + threadIdx.x;
    if (i < NN * NHEADS) g_DEN[i] = __fdividef(0.25f, g_DEN[i] + 1e-16f);
}

// ---------------- pass B: scatter messages (head-mean folded into alpha) -------
__global__ __launch_bounds__(256) void k_edge_b() {
    const int tid = threadIdx.x;
    const int slot = tid >> 4, q = tid & 15;
    const int e = blockIdx.x * 16 + slot;
    const int src = g_SRC[e];
    const int dst = g_DST[e];

    const float4 p4 = *(const float4*)(g_P + (size_t)e * 4);
    const float4 d4 = *(const float4*)(g_DEN + (size_t)dst * 4);
    const float al0 = p4.x * d4.x, al1 = p4.y * d4.y;
    const float al2 = p4.z * d4.z, al3 = p4.w * d4.w;

    const float* base = g_XL + (size_t)src * NHC + q * 4;
    float4 v0 = *(const float4*)(base);
    float4 v1 = *(const float4*)(base + 64);
    float4 v2 = *(const float4*)(base + 128);
    float4 v3 = *(const float4*)(base + 192);

    float4 acc;
    acc.x = fmaf(v0.x, al0, fmaf(v1.x, al1, fmaf(v2.x, al2, v3.x * al3)));
    acc.y = fmaf(v0.y, al0, fmaf(v1.y, al1, fmaf(v2.y, al2, v3.y * al3)));
    acc.z = fmaf(v0.z, al0, fmaf(v1.z, al1, fmaf(v2.z, al2, v3.z * al3)));
    acc.w = fmaf(v0.w, al0, fmaf(v1.w, al1, fmaf(v2.w, al2, v3.w * al3)));

    atomicAdd((float4*)(g_ACC + (size_t)dst * 64 + q * 4), acc);
}

// ---------------- node update: bias, gating, leaky-relu + re-zero scratch ------
__global__ void k_node(const float* __restrict__ bias, const float* __restrict__ gates,
                       int layer, float* __restrict__ out) {
    int i = blockIdx.x * 256 + threadIdx.x;   // grid covers exactly NN*NHID
    int c = i & 63;
    float val = g_ACC[i] + bias[c];
    if (layer == 0) {
        g_A[i] = (val > 0.f) ? val : 0.01f * val;
    } else {
        float g = 1.f / (1.f + __expf(-gates[layer - 1]));
        float h = g * val + (1.f - g) * g_A[i];
        if (layer == 1) g_A[i] = (h > 0.f) ? h : 0.01f * h;
        else            out[i] = h;
    }
    g_ACC[i] = 0.f;
    if (i < NN * NHEADS) g_DEN[i] = 0.f;
}

// ---------------- host ----------------
extern "C" void kernel_launch(void* const* d_in, const int* in_sizes, int n_in,
                              void* d_out, int out_size) {
    (void)out_size;
    const float *x = 0, *edge_attr = 0, *gates = 0;
    const float *W32k[4] = {0, 0, 0, 0};  int n32k = 0;   // init_Wl, init_Wr, Wl, Wr
    const float *a256[3] = {0, 0, 0};     int n256 = 0;   // init_bl, init_br, init_att
    const float *a512[3] = {0, 0, 0};     int n512 = 0;   // bl, br, att
    const float *init_We = 0, *WeL = 0, *init_bias = 0, *biasL = 0;
    const void* ei = 0;

    for (int i = 0; i < n_in; i++) {
        const void* p = d_in[i];
        switch (in_sizes[i]) {
            case 6400000: x = (const float*)p; break;
            case 7200000: edge_attr = (const float*)p; break;
            case 1600000: ei = p; break;
            case 3:       gates = (const float*)p; break;
            case 32768:   if (n32k < 4) W32k[n32k++] = (const float*)p; break;
            case 256:     if (n256 < 3) a256[n256++] = (const float*)p; break;
            case 512:     if (n512 < 3) a512[n512++] = (const float*)p; break;
            case 2304:    init_We = (const float*)p; break;
            case 4608:    WeL = (const float*)p; break;
            case 64:      init_bias = (const float*)p; break;
            case 128:     biasL = (const float*)p; break;
            default: break;
        }
    }
    const float *Wl0 = W32k[0], *Wr0 = W32k[1], *WlL = W32k[2], *WrL = W32k[3];
    const float *bl0 = a256[0], *br0 = a256[1], *att0 = a256[2];
    const float *blL = a512[0], *brL = a512[1], *attL = a512[2];
    float* out = (float*)d_out;

    k_convert<<<NE / 256, 256>>>(ei);

    const dim3 gemm_grid(2, (NN + 127) / 128, 2);

    for (int l = 0; l < 3; l++) {
        if (l == 0) {
            k_gemm<128><<<gemm_grid, 256>>>(x, 0, Wl0, bl0, Wr0, br0);
        } else {
            const float* Wl = WlL + (size_t)(l - 1) * 64 * 256;
            const float* Wr = WrL + (size_t)(l - 1) * 64 * 256;
            const float* bl = blL + (size_t)(l - 1) * 256;
            const float* br = brL + (size_t)(l - 1) * 256;
            k_gemm<64><<<gemm_grid, 256>>>(0, 1, Wl, bl, Wr, br);
        }

        const float* We  = l ? (WeL  + (size_t)(l - 1) * 9 * 256) : init_We;
        const float* att = l ? (attL + (size_t)(l - 1) * 256)     : att0;

        k_logits<<<2368, 128>>>(edge_attr, We, att);
        k_invden<<<(NN * NHEADS + 255) / 256, 256>>>();
        k_edge_b<<<NE / 16, 256>>>();

        const float* bias = l ? (biasL + (size_t)(l - 1) * 64) : init_bias;
        k_node<<<NN * NHID / 256, 256>>>(bias, gates, l, out);
    }
}

// round 15
// speedup vs baseline: 1.1512x; 1.1512x over previous
#include <cuda_runtime.h>
#include <math.h>

#define NN      50000
#define NE      800000
#define NHEADS  4
#define NHID    64
#define NHC     256

typedef unsigned long long ull;

// ---- packed f32x2 helpers (PTX ISA 8.6, sm_100+) ----
__device__ __forceinline__ ull pk2(float lo, float hi) {
    ull r; asm("mov.b64 %0, {%1, %2};" : "=l"(r) : "f"(lo), "f"(hi)); return r;
}
__device__ __forceinline__ void upk2(float& lo, float& hi, ull v) {
    asm("mov.b64 {%0, %1}, %2;" : "=f"(lo), "=f"(hi) : "l"(v));
}
__device__ __forceinline__ ull ffma2(ull a, ull b, ull c) {
    ull d; asm("fma.rn.f32x2 %0, %1, %2, %3;" : "=l"(d) : "l"(a), "l"(b), "l"(c)); return d;
}
__device__ __forceinline__ ull fadd2(ull a, ull b) {
    ull d; asm("add.rn.f32x2 %0, %1, %2;" : "=l"(d) : "l"(a), "l"(b)); return d;
}

// ---------------- scratch (static device globals; no allocation) ----------------
// zero-initialized at module load; k_node re-zeroes g_ACC/g_DEN each layer so
// every kernel_launch call starts from zeroed scratch (graph-replay safe).
__device__ __align__(16) float g_XL [(size_t)NN * NHC];
__device__ __align__(16) float g_XR [(size_t)NN * NHC];
__device__ __align__(16) float g_P  [(size_t)NE * NHEADS];
__device__ __align__(16) float g_DEN[(size_t)NN * NHEADS];
__device__ __align__(16) float g_ACC[(size_t)NN * NHID];
__device__ __align__(16) float g_A  [(size_t)NN * NHID];
__device__ __align__(16) int   g_SRC[NE];
__device__ __align__(16) int   g_DST[NE];

// ---------------- canonicalize edge_index (handles int32 OR int64 input) -------
__global__ void k_convert(const void* __restrict__ ei_raw) {
    __shared__ int s_is64;
    const int* ei32 = (const int*)ei_raw;
    if (threadIdx.x == 0) {
        int nz = 0;
#pragma unroll
        for (int i = 0; i < 32; i++) nz |= ei32[2 * i + 1];
        s_is64 = (nz == 0);
    }
    __syncthreads();
    int e = blockIdx.x * 256 + threadIdx.x;   // grid covers exactly NE
    if (s_is64) {
        const long long* ei64 = (const long long*)ei_raw;
        g_SRC[e] = (int)ei64[e];
        g_DST[e] = (int)ei64[NE + e];
    } else {
        g_SRC[e] = ei32[e];
        g_DST[e] = ei32[NE + e];
    }
}

// ---------------- dual GEMM: O = A[M,K] @ W[K,256] + b  (packed FFMA2) --------
template <int K>
__global__ __launch_bounds__(256) void k_gemm(
    const float* __restrict__ Aext, int useA,
    const float* __restrict__ W1, const float* __restrict__ b1,
    const float* __restrict__ W2, const float* __restrict__ b2)
{
    const float* A = useA ? g_A : Aext;
    const float* W = blockIdx.z ? W2 : W1;
    const float* b = blockIdx.z ? b2 : b1;
    float*       O = blockIdx.z ? g_XR : g_XL;

    const int m0 = blockIdx.y * 128;
    const int n0 = blockIdx.x * 128;

    __shared__ __align__(16) float sA[128][20];
    __shared__ __align__(16) float sW[16][132];

    const int tid = threadIdx.x;
    const int ty = tid >> 4, tx = tid & 15;

    ull acc2[8][4];
#pragma unroll
    for (int i = 0; i < 8; i++)
#pragma unroll
        for (int p = 0; p < 4; p++) acc2[i][p] = 0ull;

    for (int kt = 0; kt < K; kt += 16) {
#pragma unroll
        for (int u = 0; u < 2; u++) {
            int slot = tid + u * 256;
            int row = slot >> 2, ch = slot & 3;
            int gr = m0 + row;
            float4 v = make_float4(0.f, 0.f, 0.f, 0.f);
            if (gr < NN) v = *(const float4*)(A + (size_t)gr * K + kt + ch * 4);
            *(float4*)&sA[row][ch * 4] = v;
        }
#pragma unroll
        for (int u = 0; u < 2; u++) {
            int slot = tid + u * 256;
            int kk = slot >> 5, nc = (slot & 31) * 4;
            float4 v = *(const float4*)(W + (size_t)(kt + kk) * NHC + n0 + nc);
            *(float4*)&sW[kk][nc] = v;
        }
        __syncthreads();

#pragma unroll
        for (int kk = 0; kk < 16; kk++) {
            float4 w0 = *(float4*)&sW[kk][tx * 8];
            float4 w1 = *(float4*)&sW[kk][tx * 8 + 4];
            ull w2[4] = { pk2(w0.x, w0.y), pk2(w0.z, w0.w),
                          pk2(w1.x, w1.y), pk2(w1.z, w1.w) };
#pragma unroll
            for (int i = 0; i < 8; i++) {
                const float av = sA[ty * 8 + i][kk];
                const ull a2 = pk2(av, av);
#pragma unroll
                for (int p = 0; p < 4; p++)
                    acc2[i][p] = ffma2(a2, w2[p], acc2[i][p]);
            }
        }
        __syncthreads();
    }

    float4 bv0 = *(const float4*)(b + n0 + tx * 8);
    float4 bv1 = *(const float4*)(b + n0 + tx * 8 + 4);
#pragma unroll
    for (int i = 0; i < 8; i++) {
        int gr = m0 + ty * 8 + i;
        if (gr < NN) {
            float a0, a1, a2v, a3, a4, a5, a6, a7;
            upk2(a0, a1, acc2[i][0]);
            upk2(a2v, a3, acc2[i][1]);
            upk2(a4, a5, acc2[i][2]);
            upk2(a6, a7, acc2[i][3]);
            float4 o0 = make_float4(a0 + bv0.x, a1 + bv0.y, a2v + bv0.z, a3 + bv0.w);
            float4 o1 = make_float4(a4 + bv1.x, a5 + bv1.y, a6 + bv1.z, a7 + bv1.w);
            float* op = O + (size_t)gr * NHC + n0 + tx * 8;
            *(float4*)op = o0;
            *(float4*)(op + 4) = o1;
        }
    }
}

// ---------------- pass A: logits -> p = exp(logit), denominator scatter --------
// R9 champion version: 64 threads per group, 2 edges per group per iteration
// (2x ILP, 4 gathers in flight), 2-stage software pipeline, 5 blocks/SM.
__global__ __launch_bounds__(128, 5) void k_logits(
    const float* __restrict__ ea,
    const float* __restrict__ We, const float* __restrict__ att)
{
    const int tid   = threadIdx.x;
    const int grp   = tid >> 6;           // 0..1
    const int quad  = tid & 63;           // channel quad
    const int ch0   = quad * 4;
    const int head  = quad >> 4;          // 0..3

    ull wepk[9][2];
#pragma unroll
    for (int k = 0; k < 9; k++) {
        float4 w = *(const float4*)(We + k * NHC + ch0);
        wepk[k][0] = pk2(w.x, w.y);
        wepk[k][1] = pk2(w.z, w.w);
    }
    const float4 att4 = *(const float4*)(att + ch0);

    const int stride = gridDim.x * 4;     // 4 edges per block-iteration
    int eA = blockIdx.x * 4 + grp * 2;    // eA even; eB = eA + 1

    // pipeline prologue: loads for the first edge pair
    int dstA = g_DST[eA],     dstB = g_DST[eA + 1];
    float4 xlA = *(const float4*)(g_XL + (size_t)g_SRC[eA] * NHC + ch0);
    float4 xrA = *(const float4*)(g_XR + (size_t)dstA * NHC + ch0);
    float4 xlB = *(const float4*)(g_XL + (size_t)g_SRC[eA + 1] * NHC + ch0);
    float4 xrB = *(const float4*)(g_XR + (size_t)dstB * NHC + ch0);

    while (eA < NE) {
        // ---- prefetch next pair (clamped; values unused past the end) ----
        const int eA_next = eA + stride;
        const int en = (eA_next < NE) ? eA_next : eA;  // NE even -> en+1 safe
        const int srcAn = __ldg(&g_SRC[en]);
        const int dstAn = __ldg(&g_DST[en]);
        const int srcBn = __ldg(&g_SRC[en + 1]);
        const int dstBn = __ldg(&g_DST[en + 1]);
        const float4 xlAn = *(const float4*)(g_XL + (size_t)srcAn * NHC + ch0);
        const float4 xrAn = *(const float4*)(g_XR + (size_t)dstAn * NHC + ch0);
        const float4 xlBn = *(const float4*)(g_XL + (size_t)srcBn * NHC + ch0);
        const float4 xrBn = *(const float4*)(g_XR + (size_t)dstBn * NHC + ch0);

        // ---- projections (seeded with xl+xr), two independent chains ----
        ull evA01 = fadd2(pk2(xlA.x, xlA.y), pk2(xrA.x, xrA.y));
        ull evA23 = fadd2(pk2(xlA.z, xlA.w), pk2(xrA.z, xrA.w));
        ull evB01 = fadd2(pk2(xlB.x, xlB.y), pk2(xrB.x, xrB.y));
        ull evB23 = fadd2(pk2(xlB.z, xlB.w), pk2(xrB.z, xrB.w));
        const float* eapA = ea + (size_t)eA * 9;
        const float* eapB = eapA + 9;
#pragma unroll
        for (int k = 0; k < 9; k++) {
            const float aA = __ldg(eapA + k);
            const float aB = __ldg(eapB + k);
            const ull aA2 = pk2(aA, aA);
            const ull aB2 = pk2(aB, aB);
            evA01 = ffma2(aA2, wepk[k][0], evA01);
            evA23 = ffma2(aA2, wepk[k][1], evA23);
            evB01 = ffma2(aB2, wepk[k][0], evB01);
            evB23 = ffma2(aB2, wepk[k][1], evB23);
        }
        float ax, ay, az, aw, bx, by, bz, bw;
        upk2(ax, ay, evA01); upk2(az, aw, evA23);
        upk2(bx, by, evB01); upk2(bz, bw, evB23);
        ax = (ax > 0.f) ? ax : 0.2f * ax;  ay = (ay > 0.f) ? ay : 0.2f * ay;
        az = (az > 0.f) ? az : 0.2f * az;  aw = (aw > 0.f) ? aw : 0.2f * aw;
        bx = (bx > 0.f) ? bx : 0.2f * bx;  by = (by > 0.f) ? by : 0.2f * by;
        bz = (bz > 0.f) ? bz : 0.2f * bz;  bw = (bw > 0.f) ? bw : 0.2f * bw;
        float pA = att4.x * ax;
        float pB = att4.x * bx;
        pA = fmaf(att4.y, ay, pA);  pB = fmaf(att4.y, by, pB);
        pA = fmaf(att4.z, az, pA);  pB = fmaf(att4.z, bz, pB);
        pA = fmaf(att4.w, aw, pA);  pB = fmaf(att4.w, bw, pB);

        // interleaved width-16 reductions (independent -> overlap)
        pA += __shfl_down_sync(0xffffffffu, pA, 8, 16);
        pB += __shfl_down_sync(0xffffffffu, pB, 8, 16);
        pA += __shfl_down_sync(0xffffffffu, pA, 4, 16);
        pB += __shfl_down_sync(0xffffffffu, pB, 4, 16);
        pA += __shfl_down_sync(0xffffffffu, pA, 2, 16);
        pB += __shfl_down_sync(0xffffffffu, pB, 2, 16);
        pA += __shfl_down_sync(0xffffffffu, pA, 1, 16);
        pB += __shfl_down_sync(0xffffffffu, pB, 1, 16);

        if ((quad & 15) == 0) {            // reduce root per head
            const float expA = __expf(pA);
            const float expB = __expf(pB);
            g_P[(size_t)eA * NHEADS + head] = expA;
            g_P[(size_t)(eA + 1) * NHEADS + head] = expB;
            atomicAdd(&g_DEN[(size_t)dstA * NHEADS + head], expA);
            atomicAdd(&g_DEN[(size_t)dstB * NHEADS + head], expB);
        }

        // ---- rotate pipeline ----
        eA = eA_next;
        dstA = dstAn;  dstB = dstBn;
        xlA = xlAn;    xrA = xrAn;
        xlB = xlBn;    xrB = xrBn;
    }
}

// ---------------- invert denominators (fold 1/H head-mean in) ----------------
__global__ void k_invden() {
    int i = blockIdx.x * 256 + threadIdx.x;
    if (i < NN * NHEADS) g_DEN[i] = __fdividef(0.25f, g_DEN[i] + 1e-16f);
}

// ---------------- pass B: scatter messages (head-mean folded into alpha) -------
__global__ __launch_bounds__(256) void k_edge_b() {
    const int tid = threadIdx.x;
    const int slot = tid >> 4, q = tid & 15;
    const int e = blockIdx.x * 16 + slot;
    const int src = g_SRC[e];
    const int dst = g_DST[e];

    const float4 p4 = *(const float4*)(g_P + (size_t)e * 4);
    const float4 d4 = *(const float4*)(g_DEN + (size_t)dst * 4);
    const float al0 = p4.x * d4.x, al1 = p4.y * d4.y;
    const float al2 = p4.z * d4.z, al3 = p4.w * d4.w;

    const float* base = g_XL + (size_t)src * NHC + q * 4;
    float4 v0 = *(const float4*)(base);
    float4 v1 = *(const float4*)(base + 64);
    float4 v2 = *(const float4*)(base + 128);
    float4 v3 = *(const float4*)(base + 192);

    float4 acc;
    acc.x = fmaf(v0.x, al0, fmaf(v1.x, al1, fmaf(v2.x, al2, v3.x * al3)));
    acc.y = fmaf(v0.y, al0, fmaf(v1.y, al1, fmaf(v2.y, al2, v3.y * al3)));
    acc.z = fmaf(v0.z, al0, fmaf(v1.z, al1, fmaf(v2.z, al2, v3.z * al3)));
    acc.w = fmaf(v0.w, al0, fmaf(v1.w, al1, fmaf(v2.w, al2, v3.w * al3)));

    atomicAdd((float4*)(g_ACC + (size_t)dst * 64 + q * 4), acc);
}

// ---------------- node update: bias, gating, leaky-relu + re-zero scratch ------
__global__ void k_node(const float* __restrict__ bias, const float* __restrict__ gates,
                       int layer, float* __restrict__ out) {
    int i = blockIdx.x * 256 + threadIdx.x;   // grid covers exactly NN*NHID
    int c = i & 63;
    float val = g_ACC[i] + bias[c];
    if (layer == 0) {
        g_A[i] = (val > 0.f) ? val : 0.01f * val;
    } else {
        float g = 1.f / (1.f + __expf(-gates[layer - 1]));
        float h = g * val + (1.f - g) * g_A[i];
        if (layer == 1) g_A[i] = (h > 0.f) ? h : 0.01f * h;
        else            out[i] = h;
    }
    g_ACC[i] = 0.f;
    if (i < NN * NHEADS) g_DEN[i] = 0.f;
}

// ---------------- host ----------------
extern "C" void kernel_launch(void* const* d_in, const int* in_sizes, int n_in,
                              void* d_out, int out_size) {
    (void)out_size;
    const float *x = 0, *edge_attr = 0, *gates = 0;
    const float *W32k[4] = {0, 0, 0, 0};  int n32k = 0;   // init_Wl, init_Wr, Wl, Wr
    const float *a256[3] = {0, 0, 0};     int n256 = 0;   // init_bl, init_br, init_att
    const float *a512[3] = {0, 0, 0};     int n512 = 0;   // bl, br, att
    const float *init_We = 0, *WeL = 0, *init_bias = 0, *biasL = 0;
    const void* ei = 0;

    for (int i = 0; i < n_in; i++) {
        const void* p = d_in[i];
        switch (in_sizes[i]) {
            case 6400000: x = (const float*)p; break;
            case 7200000: edge_attr = (const float*)p; break;
            case 1600000: ei = p; break;
            case 3:       gates = (const float*)p; break;
            case 32768:   if (n32k < 4) W32k[n32k++] = (const float*)p; break;
            case 256:     if (n256 < 3) a256[n256++] = (const float*)p; break;
            case 512:     if (n512 < 3) a512[n512++] = (const float*)p; break;
            case 2304:    init_We = (const float*)p; break;
            case 4608:    WeL = (const float*)p; break;
            case 64:      init_bias = (const float*)p; break;
            case 128:     biasL = (const float*)p; break;
            default: break;
        }
    }
    const float *Wl0 = W32k[0], *Wr0 = W32k[1], *WlL = W32k[2], *WrL = W32k[3];
    const float *bl0 = a256[0], *br0 = a256[1], *att0 = a256[2];
    const float *blL = a512[0], *brL = a512[1], *attL = a512[2];
    float* out = (float*)d_out;

    k_convert<<<NE / 256, 256>>>(ei);

    const dim3 gemm_grid(2, (NN + 127) / 128, 2);

    for (int l = 0; l < 3; l++) {
        if (l == 0) {
            k_gemm<128><<<gemm_grid, 256>>>(x, 0, Wl0, bl0, Wr0, br0);
        } else {
            const float* Wl = WlL + (size_t)(l - 1) * 64 * 256;
            const float* Wr = WrL + (size_t)(l - 1) * 64 * 256;
            const float* bl = blL + (size_t)(l - 1) * 256;
            const float* br = brL + (size_t)(l - 1) * 256;
            k_gemm<64><<<gemm_grid, 256>>>(0, 1, Wl, bl, Wr, br);
        }

        const float* We  = l ? (WeL  + (size_t)(l - 1) * 9 * 256) : init_We;
        const float* att = l ? (attL + (size_t)(l - 1) * 256)     : att0;

        k_logits<<<2368, 128>>>(edge_attr, We, att);
        k_invden<<<(NN * NHEADS + 255) / 256, 256>>>();
        k_edge_b<<<NE / 16, 256>>>();

        const float* bias = l ? (biasL + (size_t)(l - 1) * 64) : init_bias;
        k_node<<<NN * NHID / 256, 256>>>(bias, gates, l, out);
    }
}